// round 2
// baseline (speedup 1.0000x reference)
#include <cuda_runtime.h>

namespace {
constexpr int B = 16;
constexpr int L = 1024;
constexpr int H = 512;
constexpr int V = 32000;
constexpr int HALF = 256;
constexpr int TOK = B * L;           // 16384
constexpr float ALPHA_C = 0.05f;     // 1 - 0.95
constexpr float EPS_LN_C = 1e-5f;
constexpr float EPS_NORM_C = 1e-12f;
}

// ---------------- f32x2 packed-math helpers ----------------
__device__ __forceinline__ unsigned long long f2pack(float x, float y) {
    unsigned long long r;
    asm("mov.b64 %0, {%1, %2};" : "=l"(r) : "f"(x), "f"(y));
    return r;
}
__device__ __forceinline__ unsigned long long f2dup(float x) { return f2pack(x, x); }
__device__ __forceinline__ void f2unpack(unsigned long long v, float& x, float& y) {
    asm("mov.b64 {%0, %1}, %2;" : "=f"(x), "=f"(y) : "l"(v));
}
__device__ __forceinline__ unsigned long long f2fma(unsigned long long a,
                                                    unsigned long long b,
                                                    unsigned long long c) {
    unsigned long long d;
    asm("fma.rn.f32x2 %0, %1, %2, %3;" : "=l"(d) : "l"(a), "l"(b), "l"(c));
    return d;
}

// ---------------- scratch (static device globals; no allocation) ----------------
__device__ float g_h0[TOK * H];            // embed gather output     (32 MB)
__device__ float g_ff1[TOK * 2 * H];       // FFN hidden              (64 MB)
__device__ float g_y2[TOK * H];            // FFN output (pre-LN)     (32 MB)
__device__ float g_h[TOK * H];             // post-LN hidden          (32 MB)
__device__ float g_kn[2 * L * B * HALF];   // keys -> normalized keys (32 MB), layout [m][l][b][i]
__device__ float g_nrm[2 * L * B];         // clamped norms, layout [m][l][b]
__device__ float g_c[B * H];               // context  [b][m*HALF+i]
__device__ float g_r[B * H];               // readout projection

// ---------------- embedding gather ----------------
__global__ void k_gather(const int* __restrict__ seq, const float* __restrict__ embed,
                         float* __restrict__ out) {
    int t = blockIdx.x;                    // token index (b*L + l)
    int v = seq[t];
    const float4* src = reinterpret_cast<const float4*>(embed + (size_t)v * H);
    float4* dst = reinterpret_cast<float4*>(out + (size_t)t * H);
    dst[threadIdx.x] = src[threadIdx.x];   // 128 threads * float4 = 512 floats
}

// ---------------- fp32 SGEMM via FFMA2: C[m,n] = A[m,:] . W[n,:] ----------------
// 128x128 tile, BK=16, double-buffered smem, A stored pre-duplicated for f32x2.
// MODE 0: +bias; MODE 1: +bias, relu; MODE 2: no bias, scatter to [l][b][n] layout
__device__ __forceinline__ void compute_tile(const unsigned long long* __restrict__ As2p,
                                             const float* __restrict__ Bsp,
                                             unsigned long long acc[8][4],
                                             int tr, int tc) {
#pragma unroll
    for (int kk = 0; kk < 16; ++kk) {
        const unsigned long long* arow = As2p + kk * 128 + tr * 8;
        ulonglong2 A01 = *reinterpret_cast<const ulonglong2*>(arow + 0);
        ulonglong2 A23 = *reinterpret_cast<const ulonglong2*>(arow + 2);
        ulonglong2 A45 = *reinterpret_cast<const ulonglong2*>(arow + 4);
        ulonglong2 A67 = *reinterpret_cast<const ulonglong2*>(arow + 6);
        const float* brow = Bsp + kk * 128 + tc * 8;
        float4 bv0 = *reinterpret_cast<const float4*>(brow);
        float4 bv1 = *reinterpret_cast<const float4*>(brow + 4);
        unsigned long long bb[4];
        bb[0] = f2pack(bv0.x, bv0.y);
        bb[1] = f2pack(bv0.z, bv0.w);
        bb[2] = f2pack(bv1.x, bv1.y);
        bb[3] = f2pack(bv1.z, bv1.w);
        unsigned long long aa[8];
        aa[0] = A01.x; aa[1] = A01.y; aa[2] = A23.x; aa[3] = A23.y;
        aa[4] = A45.x; aa[5] = A45.y; aa[6] = A67.x; aa[7] = A67.y;
#pragma unroll
        for (int i = 0; i < 8; ++i)
#pragma unroll
            for (int j = 0; j < 4; ++j)
                acc[i][j] = f2fma(aa[i], bb[j], acc[i][j]);
    }
}

template <int MODE>
__global__ void __launch_bounds__(256) k_gemm(const float* __restrict__ A,
                                              const float* __restrict__ W,
                                              const float* __restrict__ bias,
                                              float* __restrict__ C,
                                              int N, int K) {
    __shared__ unsigned long long As2[2][16 * 128];  // A pre-duplicated: 32 KB
    __shared__ float Bs[2][16 * 128];                // 16 KB  (total = 48 KB exactly)

    const int tid = threadIdx.x;
    const int bm = blockIdx.y * 128;
    const int bn = blockIdx.x * 128;
    const int tr = tid >> 4;        // 0..15
    const int tc = tid & 15;        // 0..15
    const int lrow = tid >> 1;      // 0..127
    const int lh = (tid & 1) * 8;   // 0 or 8

    const float* Ap = A + (size_t)(bm + lrow) * K + lh;
    const float* Wp = W + (size_t)(bn + lrow) * K + lh;

    unsigned long long acc[8][4];
#pragma unroll
    for (int i = 0; i < 8; ++i)
#pragma unroll
        for (int j = 0; j < 4; ++j) acc[i][j] = 0ull;

    float4 a0, a1, b0, b1;  // staging registers
    // prologue: tile 0
    a0 = *reinterpret_cast<const float4*>(Ap);
    a1 = *reinterpret_cast<const float4*>(Ap + 4);
    b0 = *reinterpret_cast<const float4*>(Wp);
    b1 = *reinterpret_cast<const float4*>(Wp + 4);
    {
        unsigned long long* as = As2[0];
        float* bs = Bs[0];
        as[(lh + 0) * 128 + lrow] = f2dup(a0.x);
        as[(lh + 1) * 128 + lrow] = f2dup(a0.y);
        as[(lh + 2) * 128 + lrow] = f2dup(a0.z);
        as[(lh + 3) * 128 + lrow] = f2dup(a0.w);
        as[(lh + 4) * 128 + lrow] = f2dup(a1.x);
        as[(lh + 5) * 128 + lrow] = f2dup(a1.y);
        as[(lh + 6) * 128 + lrow] = f2dup(a1.z);
        as[(lh + 7) * 128 + lrow] = f2dup(a1.w);
        bs[(lh + 0) * 128 + lrow] = b0.x;
        bs[(lh + 1) * 128 + lrow] = b0.y;
        bs[(lh + 2) * 128 + lrow] = b0.z;
        bs[(lh + 3) * 128 + lrow] = b0.w;
        bs[(lh + 4) * 128 + lrow] = b1.x;
        bs[(lh + 5) * 128 + lrow] = b1.y;
        bs[(lh + 6) * 128 + lrow] = b1.z;
        bs[(lh + 7) * 128 + lrow] = b1.w;
    }
    __syncthreads();

    int p = 0;
    for (int kt = 16; kt < K; kt += 16) {
        // fetch next tile into registers (latency hidden under compute)
        a0 = *reinterpret_cast<const float4*>(Ap + kt);
        a1 = *reinterpret_cast<const float4*>(Ap + kt + 4);
        b0 = *reinterpret_cast<const float4*>(Wp + kt);
        b1 = *reinterpret_cast<const float4*>(Wp + kt + 4);

        compute_tile(As2[p], Bs[p], acc, tr, tc);

        {
            unsigned long long* as = As2[p ^ 1];
            float* bs = Bs[p ^ 1];
            as[(lh + 0) * 128 + lrow] = f2dup(a0.x);
            as[(lh + 1) * 128 + lrow] = f2dup(a0.y);
            as[(lh + 2) * 128 + lrow] = f2dup(a0.z);
            as[(lh + 3) * 128 + lrow] = f2dup(a0.w);
            as[(lh + 4) * 128 + lrow] = f2dup(a1.x);
            as[(lh + 5) * 128 + lrow] = f2dup(a1.y);
            as[(lh + 6) * 128 + lrow] = f2dup(a1.z);
            as[(lh + 7) * 128 + lrow] = f2dup(a1.w);
            bs[(lh + 0) * 128 + lrow] = b0.x;
            bs[(lh + 1) * 128 + lrow] = b0.y;
            bs[(lh + 2) * 128 + lrow] = b0.z;
            bs[(lh + 3) * 128 + lrow] = b0.w;
            bs[(lh + 4) * 128 + lrow] = b1.x;
            bs[(lh + 5) * 128 + lrow] = b1.y;
            bs[(lh + 6) * 128 + lrow] = b1.z;
            bs[(lh + 7) * 128 + lrow] = b1.w;
        }
        __syncthreads();
        p ^= 1;
    }
    compute_tile(As2[p], Bs[p], acc, tr, tc);

    // unpack accumulators
    float accf[8][8];
#pragma unroll
    for (int i = 0; i < 8; ++i)
#pragma unroll
        for (int j = 0; j < 4; ++j)
            f2unpack(acc[i][j], accf[i][2 * j], accf[i][2 * j + 1]);

    if (MODE == 2) {
        // scatter: token row t -> (b = t>>10, l = t&1023), dst = ((l*B + b)*HALF + n)
#pragma unroll
        for (int i = 0; i < 8; ++i) {
            int grow = bm + tr * 8 + i;
            int b_ = grow >> 10;
            int l_ = grow & 1023;
            float* dst = C + ((size_t)l_ * B + b_) * HALF + bn + tc * 8;
            *reinterpret_cast<float4*>(dst) =
                make_float4(accf[i][0], accf[i][1], accf[i][2], accf[i][3]);
            *reinterpret_cast<float4*>(dst + 4) =
                make_float4(accf[i][4], accf[i][5], accf[i][6], accf[i][7]);
        }
    } else {
        float bv[8];
#pragma unroll
        for (int j = 0; j < 8; ++j) bv[j] = bias[bn + tc * 8 + j];
#pragma unroll
        for (int i = 0; i < 8; ++i) {
            float o[8];
#pragma unroll
            for (int j = 0; j < 8; ++j) {
                float v = accf[i][j] + bv[j];
                if (MODE == 1) v = fmaxf(v, 0.f);
                o[j] = v;
            }
            float* dst = C + (size_t)(bm + tr * 8 + i) * N + bn + tc * 8;
            *reinterpret_cast<float4*>(dst) = make_float4(o[0], o[1], o[2], o[3]);
            *reinterpret_cast<float4*>(dst + 4) = make_float4(o[4], o[5], o[6], o[7]);
        }
    }
}

// ---------------- residual + LayerNorm (warp per row) ----------------
__global__ void k_ln(const float* __restrict__ y2, const float* __restrict__ h0,
                     const float* __restrict__ gamma, const float* __restrict__ beta,
                     float* __restrict__ out) {
    int warp = threadIdx.x >> 5, lane = threadIdx.x & 31;
    int row = blockIdx.x * 8 + warp;
    const float4* a = reinterpret_cast<const float4*>(y2 + (size_t)row * H);
    const float4* hb = reinterpret_cast<const float4*>(h0 + (size_t)row * H);
    float x[16];
    float s = 0.f, s2 = 0.f;
#pragma unroll
    for (int i = 0; i < 4; ++i) {
        float4 u = a[lane + i * 32];
        float4 v = hb[lane + i * 32];
        float t0 = u.x + v.x, t1 = u.y + v.y, t2 = u.z + v.z, t3 = u.w + v.w;
        x[i * 4 + 0] = t0; x[i * 4 + 1] = t1; x[i * 4 + 2] = t2; x[i * 4 + 3] = t3;
        s += t0 + t1 + t2 + t3;
        s2 += t0 * t0 + t1 * t1 + t2 * t2 + t3 * t3;
    }
#pragma unroll
    for (int off = 16; off > 0; off >>= 1) {
        s += __shfl_xor_sync(0xffffffffu, s, off);
        s2 += __shfl_xor_sync(0xffffffffu, s2, off);
    }
    float mu = s * (1.f / H);
    float var = s2 * (1.f / H) - mu * mu;
    float rstd = rsqrtf(var + EPS_LN_C);
    float4* o = reinterpret_cast<float4*>(out + (size_t)row * H);
    const float4* g4 = reinterpret_cast<const float4*>(gamma);
    const float4* b4 = reinterpret_cast<const float4*>(beta);
#pragma unroll
    for (int i = 0; i < 4; ++i) {
        float4 gg = __ldg(g4 + lane + i * 32);
        float4 bb = __ldg(b4 + lane + i * 32);
        float4 r;
        r.x = (x[i * 4 + 0] - mu) * rstd * gg.x + bb.x;
        r.y = (x[i * 4 + 1] - mu) * rstd * gg.y + bb.y;
        r.z = (x[i * 4 + 2] - mu) * rstd * gg.z + bb.z;
        r.w = (x[i * 4 + 3] - mu) * rstd * gg.w + bb.w;
        o[lane + i * 32] = r;
    }
}

// ---------------- L2-normalize key rows in place, save clamped norm ----------------
__global__ void k_norm(float* __restrict__ kn, float* __restrict__ nrm) {
    int warp = threadIdx.x >> 5, lane = threadIdx.x & 31;
    int row = blockIdx.x * 8 + warp;               // 0 .. 2*L*B-1
    float4* p4 = reinterpret_cast<float4*>(kn + (size_t)row * HALF);
    float4 v0 = p4[lane];
    float4 v1 = p4[lane + 32];
    float s = v0.x * v0.x + v0.y * v0.y + v0.z * v0.z + v0.w * v0.w
            + v1.x * v1.x + v1.y * v1.y + v1.z * v1.z + v1.w * v1.w;
#pragma unroll
    for (int off = 16; off > 0; off >>= 1) s += __shfl_xor_sync(0xffffffffu, s, off);
    float n = sqrtf(s);
    float nc = fmaxf(n, EPS_NORM_C);
    float inv = 1.f / nc;
    v0.x *= inv; v0.y *= inv; v0.z *= inv; v0.w *= inv;
    v1.x *= inv; v1.y *= inv; v1.z *= inv; v1.w *= inv;
    p4[lane] = v0;
    p4[lane + 32] = v1;
    if (lane == 0) nrm[row] = nc;
}

// ---------------- the EMA scan: warp handles 8 independent M-rows ----------------
__global__ void __launch_bounds__(128) k_scan(const float* __restrict__ kn_all,
                                              const float* __restrict__ nrm_all,
                                              float* __restrict__ cbuf) {
    const int lane = threadIdx.x & 31;
    const int warp = threadIdx.x >> 5;
    const int pair = blockIdx.x >> 3;      // 0..31 : (m,b)
    const int cta8 = blockIdx.x & 7;
    const int m = pair >> 4;
    const int b = pair & 15;
    const int grp = cta8 * 4 + warp;       // row group 0..31
    const int r0 = grp * 8;

    const float* __restrict__ kn = kn_all + ((size_t)m * L * B + b) * HALF;
    const float* __restrict__ nr = nrm_all + (size_t)m * L * B + b;

    float Mx[8][8];
#pragma unroll
    for (int r = 0; r < 8; ++r)
#pragma unroll
        for (int q = 0; q < 8; ++q) Mx[r][q] = 0.f;

    float k[8];
    float nrm;
    {
        const float4* p = reinterpret_cast<const float4*>(kn + lane * 8);
        float4 u = __ldg(p), v = __ldg(p + 1);
        k[0] = u.x; k[1] = u.y; k[2] = u.z; k[3] = u.w;
        k[4] = v.x; k[5] = v.y; k[6] = v.z; k[7] = v.w;
        nrm = __ldg(nr);
    }

    for (int t = 0; t < L - 1; ++t) {
        float cur[8];
#pragma unroll
        for (int q = 0; q < 8; ++q) cur[q] = k[q];
        float cn = nrm;
        {   // prefetch step t+1 (valid up to t+1 = L-1, used by the final query)
            const float4* p = reinterpret_cast<const float4*>(
                kn + (size_t)(t + 1) * (B * HALF) + lane * 8);
            float4 u = __ldg(p), v = __ldg(p + 1);
            k[0] = u.x; k[1] = u.y; k[2] = u.z; k[3] = u.w;
            k[4] = v.x; k[5] = v.y; k[6] = v.z; k[7] = v.w;
            nrm = __ldg(nr + (size_t)(t + 1) * B);
        }
        float dot[8];
#pragma unroll
        for (int r = 0; r < 8; ++r) {
            float d = Mx[r][0] * cur[0];
#pragma unroll
            for (int q = 1; q < 8; ++q) d += Mx[r][q] * cur[q];
            dot[r] = d;
        }
#pragma unroll
        for (int off = 16; off > 0; off >>= 1)
#pragma unroll
            for (int r = 0; r < 8; ++r)
                dot[r] += __shfl_xor_sync(0xffffffffu, dot[r], off);
#pragma unroll
        for (int r = 0; r < 8; ++r) {
            float kni = __shfl_sync(0xffffffffu, cur[r], grp); // kn[r0+r]
            float coef = ALPHA_C * (kni * cn - dot[r]);
#pragma unroll
            for (int q = 0; q < 8; ++q) Mx[r][q] += coef * cur[q];
        }
    }

    // query with unnormalized last key: c_i = (M_i . kn(L-1)) * nrm(L-1)
    float dot[8];
#pragma unroll
    for (int r = 0; r < 8; ++r) {
        float d = Mx[r][0] * k[0];
#pragma unroll
        for (int q = 1; q < 8; ++q) d += Mx[r][q] * k[q];
        dot[r] = d;
    }
#pragma unroll
    for (int off = 16; off > 0; off >>= 1)
#pragma unroll
        for (int r = 0; r < 8; ++r)
            dot[r] += __shfl_xor_sync(0xffffffffu, dot[r], off);
    if (lane == 0) {
#pragma unroll
        for (int r = 0; r < 8; ++r)
            cbuf[b * H + m * HALF + r0 + r] = dot[r] * nrm;
    }
}

// ---------------- r = c @ rp_w^T + rp_b  ([16,512] x [512,512]) ----------------
__global__ void k_rp(const float* __restrict__ c, const float* __restrict__ W,
                     const float* __restrict__ bias, float* __restrict__ r) {
    __shared__ float cs[B * (H + 1)];
    for (int i = threadIdx.x; i < B * H; i += 256) {
        int bb = i >> 9, hh = i & 511;
        cs[bb * (H + 1) + hh] = c[i];
    }
    __syncthreads();
    int g = blockIdx.x * 16 + (threadIdx.x >> 4);
    int b = threadIdx.x & 15;
    const float* w = W + (size_t)g * H;
    const float* cb = &cs[b * (H + 1)];
    float acc = 0.f;
    for (int h = 0; h < H; h += 4) {
        float4 wv = __ldg(reinterpret_cast<const float4*>(w + h));
        acc += cb[h] * wv.x + cb[h + 1] * wv.y + cb[h + 2] * wv.z + cb[h + 3] * wv.w;
    }
    r[b * H + g] = acc + bias[g];
}

// ---------------- out = r @ out_w^T + out_b  ([16,512] x [32000,512]) ----------------
__global__ void k_out(const float* __restrict__ r, const float* __restrict__ W,
                      const float* __restrict__ bias, float* __restrict__ out) {
    __shared__ float rs[B * H];
    for (int i = threadIdx.x; i < B * H; i += 256) rs[i] = r[i];
    __syncthreads();
    int v = blockIdx.x * 256 + threadIdx.x;
    float acc[B];
#pragma unroll
    for (int b = 0; b < B; ++b) acc[b] = 0.f;
    const float4* w = reinterpret_cast<const float4*>(W + (size_t)v * H);
#pragma unroll 4
    for (int i = 0; i < H / 4; ++i) {
        float4 wv = __ldg(w + i);
#pragma unroll
        for (int b = 0; b < B; ++b) {
            float4 rv = *reinterpret_cast<const float4*>(&rs[b * H + i * 4]);
            acc[b] += rv.x * wv.x + rv.y * wv.y + rv.z * wv.z + rv.w * wv.w;
        }
    }
    float bb = __ldg(bias + v);
#pragma unroll
    for (int b = 0; b < B; ++b) out[(size_t)b * V + v] = acc[b] + bb;
}

// ---------------- launch ----------------
extern "C" void kernel_launch(void* const* d_in, const int* in_sizes, int n_in,
                              void* d_out, int out_size) {
    const int*   seq   = (const int*)d_in[0];
    const float* embed = (const float*)d_in[1];
    const float* ff_w1 = (const float*)d_in[2];
    const float* ff_b1 = (const float*)d_in[3];
    const float* ff_w2 = (const float*)d_in[4];
    const float* ff_b2 = (const float*)d_in[5];
    const float* gamma = (const float*)d_in[6];
    const float* beta  = (const float*)d_in[7];
    const float* sem_w = (const float*)d_in[8];
    const float* epi_w = (const float*)d_in[9];
    const float* rp_w  = (const float*)d_in[10];
    const float* rp_b  = (const float*)d_in[11];
    const float* out_w = (const float*)d_in[12];
    const float* out_b = (const float*)d_in[13];
    float* out = (float*)d_out;

    float *h0, *ff1, *y2, *h, *kn, *nrm, *c, *r;
    cudaGetSymbolAddress((void**)&h0,  g_h0);
    cudaGetSymbolAddress((void**)&ff1, g_ff1);
    cudaGetSymbolAddress((void**)&y2,  g_y2);
    cudaGetSymbolAddress((void**)&h,   g_h);
    cudaGetSymbolAddress((void**)&kn,  g_kn);
    cudaGetSymbolAddress((void**)&nrm, g_nrm);
    cudaGetSymbolAddress((void**)&c,   g_c);
    cudaGetSymbolAddress((void**)&r,   g_r);

    // 1. embedding gather
    k_gather<<<TOK, 128>>>(seq, embed, h0);
    // 2. FFN up (relu)
    k_gemm<1><<<dim3(2 * H / 128, TOK / 128), 256>>>(h0, ff_w1, ff_b1, ff1, 2 * H, H);
    // 3. FFN down
    k_gemm<0><<<dim3(H / 128, TOK / 128), 256>>>(ff1, ff_w2, ff_b2, y2, H, 2 * H);
    // 4. residual + layernorm
    k_ln<<<TOK / 8, 256>>>(y2, h0, gamma, beta, h);
    // 5+6. key projections, scattered to [l][b][c]
    k_gemm<2><<<dim3(HALF / 128, TOK / 128), 256>>>(h, sem_w, nullptr, kn, HALF, H);
    k_gemm<2><<<dim3(HALF / 128, TOK / 128), 256>>>(h, epi_w, nullptr,
                                                    kn + (size_t)L * B * HALF, HALF, H);
    // 7. normalize keys in place, stash clamped norms
    k_norm<<<(2 * L * B) / 8, 256>>>(kn, nrm);
    // 8. the sequential scan (row-parallel)
    k_scan<<<256, 128>>>(kn, nrm, c);
    // 9. readout projection
    k_rp<<<H / 16, 256>>>(c, rp_w, rp_b, r);
    // 10. logits
    k_out<<<V / 256, 256>>>(r, out_w, out_b, out);
}

// round 3
// speedup vs baseline: 2.8626x; 2.8626x over previous
#include <cuda_runtime.h>
#include <cstdint>

namespace {
constexpr int B = 16;
constexpr int L = 1024;
constexpr int H = 512;
constexpr int V = 32000;
constexpr int HALF = 256;
constexpr int TOK = B * L;           // 16384
constexpr float ALPHA_C = 0.05f;     // 1 - 0.95
constexpr float EPS_LN_C = 1e-5f;
constexpr float EPS_NORM_C = 1e-12f;
}

// ---------------- scratch (static device globals; no allocation) ----------------
__device__ float g_h0[TOK * H];            // embed gather output
__device__ float g_ff1[TOK * 2 * H];       // FFN hidden
__device__ float g_y2[TOK * H];            // FFN output (pre-LN)
__device__ float g_h[TOK * H];             // post-LN hidden
__device__ float g_kn[2 * L * B * HALF];   // normalized keys, layout [m][l][b][i]
__device__ float g_nrm[2 * L * B];         // clamped norms, layout [m][l][b]
__device__ float g_c[B * H];               // context  [b][m*HALF+i]
__device__ float g_r[B * H];               // readout projection

// ---------------- tensor-core helpers ----------------
__device__ __forceinline__ uint32_t to_tf32(float f) {
    uint32_t r;
    asm("cvt.rna.tf32.f32 %0, %1;" : "=r"(r) : "f"(f));
    return r;
}
__device__ __forceinline__ uint32_t smem_u32(const void* p) {
    return (uint32_t)__cvta_generic_to_shared(p);
}
__device__ __forceinline__ void ldsm_x4(uint32_t& r0, uint32_t& r1, uint32_t& r2,
                                        uint32_t& r3, uint32_t a) {
    asm volatile("ldmatrix.sync.aligned.m8n8.x4.shared.b16 {%0,%1,%2,%3}, [%4];"
                 : "=r"(r0), "=r"(r1), "=r"(r2), "=r"(r3) : "r"(a));
}
__device__ __forceinline__ void ldsm_x2(uint32_t& r0, uint32_t& r1, uint32_t a) {
    asm volatile("ldmatrix.sync.aligned.m8n8.x2.shared.b16 {%0,%1}, [%2];"
                 : "=r"(r0), "=r"(r1) : "r"(a));
}
__device__ __forceinline__ void mma_tf32(float* d, const uint32_t* a, const uint32_t* b) {
    asm volatile(
        "mma.sync.aligned.m16n8k8.row.col.f32.tf32.tf32.f32 "
        "{%0,%1,%2,%3},{%4,%5,%6,%7},{%8,%9},{%0,%1,%2,%3};"
        : "+f"(d[0]), "+f"(d[1]), "+f"(d[2]), "+f"(d[3])
        : "r"(a[0]), "r"(a[1]), "r"(a[2]), "r"(a[3]), "r"(b[0]), "r"(b[1]));
}

// ---------------- embedding gather ----------------
__global__ void k_gather(const int* __restrict__ seq, const float* __restrict__ embed,
                         float* __restrict__ out) {
    int t = blockIdx.x;
    int v = seq[t];
    const float4* src = reinterpret_cast<const float4*>(embed + (size_t)v * H);
    float4* dst = reinterpret_cast<float4*>(out + (size_t)t * H);
    dst[threadIdx.x] = src[threadIdx.x];
}

// ---------------- TF32 tensor GEMM: C[m,n] = A[m,:] . W[n,:] ----------------
// 128x128 tile, BK=16, double-buffered K-major smem (stride 20), ldmatrix + mma.
// MODE 0: +bias; MODE 1: +bias, relu; MODE 2: no bias, scatter to [l][b][n]
constexpr int SSTR = 20;   // smem row stride in words (16 + 4 pad)

template <int MODE>
__global__ void __launch_bounds__(256, 2) k_gemm(const float* __restrict__ A,
                                                 const float* __restrict__ W,
                                                 const float* __restrict__ bias,
                                                 float* __restrict__ C,
                                                 int N, int K) {
    __shared__ uint32_t As[2][128 * SSTR];   // 10 KB each
    __shared__ uint32_t Ws[2][128 * SSTR];   // total 40 KB

    const int tid = threadIdx.x;
    const int bm = blockIdx.y * 128;
    const int bn = blockIdx.x * 128;
    const int warp = tid >> 5, lane = tid & 31;
    const int wm = warp >> 2, wn = warp & 3;       // 2 x 4 warp grid
    const int g = lane >> 2, tg = lane & 3;

    // ldmatrix source lanes
    const int a_r = lane & 15;                 // row within m16 tile
    const int a_c = (lane >> 4) << 2;          // k col offset 0/4
    const int b_r = lane & 7;                  // row within n8 tile
    const int b_c = ((lane >> 3) & 1) << 2;    // k col offset 0/4

    // global loader mapping: thread -> (row lrow, k offset lk), 8 floats each matrix
    const int lrow = tid >> 1;
    const int lk = (tid & 1) * 8;
    const float* Ap = A + (size_t)(bm + lrow) * K + lk;
    const float* Wp = W + (size_t)(bn + lrow) * K + lk;

    float acc[4][4][4];
#pragma unroll
    for (int mi = 0; mi < 4; ++mi)
#pragma unroll
        for (int ni = 0; ni < 4; ++ni)
#pragma unroll
            for (int q = 0; q < 4; ++q) acc[mi][ni][q] = 0.f;

    uint32_t ar[8], wr[8];
    auto load_global = [&](int pass) {
        float4 x = __ldg(reinterpret_cast<const float4*>(Ap + pass * 16));
        float4 y = __ldg(reinterpret_cast<const float4*>(Ap + pass * 16 + 4));
        float4 u = __ldg(reinterpret_cast<const float4*>(Wp + pass * 16));
        float4 w = __ldg(reinterpret_cast<const float4*>(Wp + pass * 16 + 4));
        ar[0] = to_tf32(x.x); ar[1] = to_tf32(x.y); ar[2] = to_tf32(x.z); ar[3] = to_tf32(x.w);
        ar[4] = to_tf32(y.x); ar[5] = to_tf32(y.y); ar[6] = to_tf32(y.z); ar[7] = to_tf32(y.w);
        wr[0] = to_tf32(u.x); wr[1] = to_tf32(u.y); wr[2] = to_tf32(u.z); wr[3] = to_tf32(u.w);
        wr[4] = to_tf32(w.x); wr[5] = to_tf32(w.y); wr[6] = to_tf32(w.z); wr[7] = to_tf32(w.w);
    };
    auto store_smem = [&](int buf) {
        uint4* da = reinterpret_cast<uint4*>(&As[buf][lrow * SSTR + lk]);
        da[0] = make_uint4(ar[0], ar[1], ar[2], ar[3]);
        da[1] = make_uint4(ar[4], ar[5], ar[6], ar[7]);
        uint4* dw = reinterpret_cast<uint4*>(&Ws[buf][lrow * SSTR + lk]);
        dw[0] = make_uint4(wr[0], wr[1], wr[2], wr[3]);
        dw[1] = make_uint4(wr[4], wr[5], wr[6], wr[7]);
    };
    auto mma_pass = [&](int buf) {
#pragma unroll
        for (int ak = 0; ak < 2; ++ak) {
            int k0 = ak * 8;
            uint32_t afrag[4][4];
#pragma unroll
            for (int mi = 0; mi < 4; ++mi) {
                uint32_t addr = smem_u32(&As[buf][(wm * 64 + mi * 16 + a_r) * SSTR + k0 + a_c]);
                ldsm_x4(afrag[mi][0], afrag[mi][1], afrag[mi][2], afrag[mi][3], addr);
            }
            uint32_t bfrag[4][2];
#pragma unroll
            for (int ni = 0; ni < 4; ++ni) {
                uint32_t addr = smem_u32(&Ws[buf][(wn * 32 + ni * 8 + b_r) * SSTR + k0 + b_c]);
                ldsm_x2(bfrag[ni][0], bfrag[ni][1], addr);
            }
#pragma unroll
            for (int mi = 0; mi < 4; ++mi)
#pragma unroll
                for (int ni = 0; ni < 4; ++ni)
                    mma_tf32(acc[mi][ni], afrag[mi], bfrag[ni]);
        }
    };

    const int NPASS = K / 16;
    load_global(0);
    store_smem(0);
    __syncthreads();
    for (int p = 1; p < NPASS; ++p) {
        load_global(p);
        mma_pass((p - 1) & 1);
        store_smem(p & 1);
        __syncthreads();
    }
    mma_pass((NPASS - 1) & 1);

    // epilogue: acc reg q -> row g + (q>=2)*8, col tg*2 + (q&1)
#pragma unroll
    for (int mi = 0; mi < 4; ++mi) {
#pragma unroll
        for (int half = 0; half < 2; ++half) {
            int r = bm + wm * 64 + mi * 16 + g + half * 8;
#pragma unroll
            for (int ni = 0; ni < 4; ++ni) {
                int col = bn + wn * 32 + ni * 8 + tg * 2;
                float x = acc[mi][ni][half * 2 + 0];
                float y = acc[mi][ni][half * 2 + 1];
                if (MODE == 2) {
                    int b_ = r >> 10, l_ = r & 1023;
                    float* dst = C + ((size_t)l_ * B + b_) * HALF + col;
                    *reinterpret_cast<float2*>(dst) = make_float2(x, y);
                } else {
                    x += bias[col];
                    y += bias[col + 1];
                    if (MODE == 1) { x = fmaxf(x, 0.f); y = fmaxf(y, 0.f); }
                    float* dst = C + (size_t)r * N + col;
                    *reinterpret_cast<float2*>(dst) = make_float2(x, y);
                }
            }
        }
    }
}

// ---------------- residual + LayerNorm (warp per row) ----------------
__global__ void k_ln(const float* __restrict__ y2, const float* __restrict__ h0,
                     const float* __restrict__ gamma, const float* __restrict__ beta,
                     float* __restrict__ out) {
    int warp = threadIdx.x >> 5, lane = threadIdx.x & 31;
    int row = blockIdx.x * 8 + warp;
    const float4* a = reinterpret_cast<const float4*>(y2 + (size_t)row * H);
    const float4* hb = reinterpret_cast<const float4*>(h0 + (size_t)row * H);
    float x[16];
    float s = 0.f, s2 = 0.f;
#pragma unroll
    for (int i = 0; i < 4; ++i) {
        float4 u = a[lane + i * 32];
        float4 v = hb[lane + i * 32];
        float t0 = u.x + v.x, t1 = u.y + v.y, t2 = u.z + v.z, t3 = u.w + v.w;
        x[i * 4 + 0] = t0; x[i * 4 + 1] = t1; x[i * 4 + 2] = t2; x[i * 4 + 3] = t3;
        s += t0 + t1 + t2 + t3;
        s2 += t0 * t0 + t1 * t1 + t2 * t2 + t3 * t3;
    }
#pragma unroll
    for (int off = 16; off > 0; off >>= 1) {
        s += __shfl_xor_sync(0xffffffffu, s, off);
        s2 += __shfl_xor_sync(0xffffffffu, s2, off);
    }
    float mu = s * (1.f / H);
    float var = s2 * (1.f / H) - mu * mu;
    float rstd = rsqrtf(var + EPS_LN_C);
    float4* o = reinterpret_cast<float4*>(out + (size_t)row * H);
    const float4* g4 = reinterpret_cast<const float4*>(gamma);
    const float4* b4 = reinterpret_cast<const float4*>(beta);
#pragma unroll
    for (int i = 0; i < 4; ++i) {
        float4 gg = __ldg(g4 + lane + i * 32);
        float4 bb = __ldg(b4 + lane + i * 32);
        float4 r;
        r.x = (x[i * 4 + 0] - mu) * rstd * gg.x + bb.x;
        r.y = (x[i * 4 + 1] - mu) * rstd * gg.y + bb.y;
        r.z = (x[i * 4 + 2] - mu) * rstd * gg.z + bb.z;
        r.w = (x[i * 4 + 3] - mu) * rstd * gg.w + bb.w;
        o[lane + i * 32] = r;
    }
}

// ---------------- L2-normalize key rows in place, save clamped norm ----------------
__global__ void k_norm(float* __restrict__ kn, float* __restrict__ nrm) {
    int warp = threadIdx.x >> 5, lane = threadIdx.x & 31;
    int row = blockIdx.x * 8 + warp;               // 0 .. 2*L*B-1
    float4* p4 = reinterpret_cast<float4*>(kn + (size_t)row * HALF);
    float4 v0 = p4[lane];
    float4 v1 = p4[lane + 32];
    float s = v0.x * v0.x + v0.y * v0.y + v0.z * v0.z + v0.w * v0.w
            + v1.x * v1.x + v1.y * v1.y + v1.z * v1.z + v1.w * v1.w;
#pragma unroll
    for (int off = 16; off > 0; off >>= 1) s += __shfl_xor_sync(0xffffffffu, s, off);
    float n = sqrtf(s);
    float nc = fmaxf(n, EPS_NORM_C);
    float inv = 1.f / nc;
    v0.x *= inv; v0.y *= inv; v0.z *= inv; v0.w *= inv;
    v1.x *= inv; v1.y *= inv; v1.z *= inv; v1.w *= inv;
    p4[lane] = v0;
    p4[lane + 32] = v1;
    if (lane == 0) nrm[row] = nc;
}

// ---------------- EMA scan, backward-query form ----------------
// c = sum_t alpha * k_t * s_t ;  s_t = kn_t . v_{t+1} ;  v_t = v_{t+1} - alpha*kn_t*s_t
// v starts at the (unnormalized) final query. Blocked 4 steps via Gram correction.
__device__ __forceinline__ void scan_load4(const float* kn, const float* nr, int t0,
                                           int lane, float k4[4][8], float n4[4]) {
    const int STRD = B * HALF;
#pragma unroll
    for (int j = 0; j < 4; ++j) {
        const float4* p = reinterpret_cast<const float4*>(kn + (size_t)(t0 + j) * STRD + lane * 8);
        float4 u = __ldg(p), w = __ldg(p + 1);
        k4[j][0] = u.x; k4[j][1] = u.y; k4[j][2] = u.z; k4[j][3] = u.w;
        k4[j][4] = w.x; k4[j][5] = w.y; k4[j][6] = w.z; k4[j][7] = w.w;
        n4[j] = __ldg(nr + (size_t)(t0 + j) * B);
    }
}

__global__ void __launch_bounds__(32) k_scan(const float* __restrict__ kn_all,
                                             const float* __restrict__ nrm_all,
                                             float* __restrict__ cbuf) {
    const int lane = threadIdx.x;
    const int m = blockIdx.x >> 4;
    const int b = blockIdx.x & 15;
    const float* kn = kn_all + (size_t)m * L * B * HALF + b * HALF;
    const float* nr = nrm_all + (size_t)m * L * B + b;
    const int STRD = B * HALF;

    float v[8], cac[8];
    {
        const float4* p = reinterpret_cast<const float4*>(kn + (size_t)(L - 1) * STRD + lane * 8);
        float4 u = __ldg(p), w = __ldg(p + 1);
        float qn = __ldg(nr + (size_t)(L - 1) * B);
        v[0] = u.x * qn; v[1] = u.y * qn; v[2] = u.z * qn; v[3] = u.w * qn;
        v[4] = w.x * qn; v[5] = w.y * qn; v[6] = w.z * qn; v[7] = w.w * qn;
    }
#pragma unroll
    for (int j = 0; j < 8; ++j) cac[j] = 0.f;

    float cur[4][8], nxt[4][8], curn[4], nxtn[4];
    scan_load4(kn, nr, L - 5, lane, cur, curn);     // first block: t = L-5..L-2

    for (int t0 = L - 5; t0 >= 3; t0 -= 4) {
        bool more = (t0 > 3);
        if (more) scan_load4(kn, nr, t0 - 4, lane, nxt, nxtn);

        // 10 partial dots: u0..u3 = k_j.v ; Gram pairs
        float red[10];
#pragma unroll
        for (int q = 0; q < 10; ++q) red[q] = 0.f;
#pragma unroll
        for (int j = 0; j < 8; ++j) {
            float vj = v[j];
            float k0 = cur[0][j], k1 = cur[1][j], k2 = cur[2][j], k3 = cur[3][j];
            red[0] += k0 * vj;   // u0
            red[1] += k1 * vj;   // u1
            red[2] += k2 * vj;   // u2
            red[3] += k3 * vj;   // u3
            red[4] += k3 * k2;   // g32
            red[5] += k3 * k1;   // g31
            red[6] += k3 * k0;   // g30
            red[7] += k2 * k1;   // g21
            red[8] += k2 * k0;   // g20
            red[9] += k1 * k0;   // g10
        }
#pragma unroll
        for (int off = 16; off > 0; off >>= 1)
#pragma unroll
            for (int q = 0; q < 10; ++q)
                red[q] += __shfl_xor_sync(0xffffffffu, red[q], off);

        float s3 = red[3];
        float s2 = red[2] - ALPHA_C * red[4] * s3;
        float s1 = red[1] - ALPHA_C * (red[5] * s3 + red[7] * s2);
        float s0 = red[0] - ALPHA_C * (red[6] * s3 + red[8] * s2 + red[9] * s1);
        float w3 = curn[3] * s3, w2 = curn[2] * s2, w1 = curn[1] * s1, w0 = curn[0] * s0;
#pragma unroll
        for (int j = 0; j < 8; ++j) {
            float k0 = cur[0][j], k1 = cur[1][j], k2 = cur[2][j], k3 = cur[3][j];
            v[j] -= ALPHA_C * (k3 * s3 + k2 * s2 + k1 * s1 + k0 * s0);
            cac[j] += k3 * w3 + k2 * w2 + k1 * w1 + k0 * w0;
        }
        if (more) {
#pragma unroll
            for (int j = 0; j < 4; ++j) {
                curn[j] = nxtn[j];
#pragma unroll
                for (int q = 0; q < 8; ++q) cur[j][q] = nxt[j][q];
            }
        }
    }

    // remainder: t = 2, 1, 0 single steps
    for (int t = 2; t >= 0; --t) {
        float kt[8];
        const float4* p = reinterpret_cast<const float4*>(kn + (size_t)t * STRD + lane * 8);
        float4 u = __ldg(p), w = __ldg(p + 1);
        kt[0] = u.x; kt[1] = u.y; kt[2] = u.z; kt[3] = u.w;
        kt[4] = w.x; kt[5] = w.y; kt[6] = w.z; kt[7] = w.w;
        float nt = __ldg(nr + (size_t)t * B);
        float s = 0.f;
#pragma unroll
        for (int j = 0; j < 8; ++j) s += kt[j] * v[j];
#pragma unroll
        for (int off = 16; off > 0; off >>= 1) s += __shfl_xor_sync(0xffffffffu, s, off);
        float ws = nt * s;
#pragma unroll
        for (int j = 0; j < 8; ++j) {
            cac[j] += kt[j] * ws;
            v[j] -= ALPHA_C * s * kt[j];
        }
    }

    float* out = cbuf + b * H + m * HALF + lane * 8;
#pragma unroll
    for (int j = 0; j < 8; ++j) out[j] = ALPHA_C * cac[j];
}

// ---------------- r = c @ rp_w^T + rp_b ----------------
__global__ void k_rp(const float* __restrict__ c, const float* __restrict__ W,
                     const float* __restrict__ bias, float* __restrict__ r) {
    __shared__ float cs[B * (H + 1)];
    for (int i = threadIdx.x; i < B * H; i += 256) {
        int bb = i >> 9, hh = i & 511;
        cs[bb * (H + 1) + hh] = c[i];
    }
    __syncthreads();
    int g = blockIdx.x * 16 + (threadIdx.x >> 4);
    int b = threadIdx.x & 15;
    const float* w = W + (size_t)g * H;
    const float* cb = &cs[b * (H + 1)];
    float acc = 0.f;
    for (int h = 0; h < H; h += 4) {
        float4 wv = __ldg(reinterpret_cast<const float4*>(w + h));
        acc += cb[h] * wv.x + cb[h + 1] * wv.y + cb[h + 2] * wv.z + cb[h + 3] * wv.w;
    }
    r[b * H + g] = acc + bias[g];
}

// ---------------- out = r @ out_w^T + out_b ----------------
__global__ void k_out(const float* __restrict__ r, const float* __restrict__ W,
                      const float* __restrict__ bias, float* __restrict__ out) {
    __shared__ float rs[B * H];
    for (int i = threadIdx.x; i < B * H; i += 256) rs[i] = r[i];
    __syncthreads();
    int v = blockIdx.x * 256 + threadIdx.x;
    float acc[B];
#pragma unroll
    for (int b = 0; b < B; ++b) acc[b] = 0.f;
    const float4* w = reinterpret_cast<const float4*>(W + (size_t)v * H);
#pragma unroll 4
    for (int i = 0; i < H / 4; ++i) {
        float4 wv = __ldg(w + i);
#pragma unroll
        for (int b = 0; b < B; ++b) {
            float4 rv = *reinterpret_cast<const float4*>(&rs[b * H + i * 4]);
            acc[b] += rv.x * wv.x + rv.y * wv.y + rv.z * wv.z + rv.w * wv.w;
        }
    }
    float bb = __ldg(bias + v);
#pragma unroll
    for (int b = 0; b < B; ++b) out[(size_t)b * V + v] = acc[b] + bb;
}

// ---------------- launch ----------------
extern "C" void kernel_launch(void* const* d_in, const int* in_sizes, int n_in,
                              void* d_out, int out_size) {
    const int*   seq   = (const int*)d_in[0];
    const float* embed = (const float*)d_in[1];
    const float* ff_w1 = (const float*)d_in[2];
    const float* ff_b1 = (const float*)d_in[3];
    const float* ff_w2 = (const float*)d_in[4];
    const float* ff_b2 = (const float*)d_in[5];
    const float* gamma = (const float*)d_in[6];
    const float* beta  = (const float*)d_in[7];
    const float* sem_w = (const float*)d_in[8];
    const float* epi_w = (const float*)d_in[9];
    const float* rp_w  = (const float*)d_in[10];
    const float* rp_b  = (const float*)d_in[11];
    const float* out_w = (const float*)d_in[12];
    const float* out_b = (const float*)d_in[13];
    float* out = (float*)d_out;

    float *h0, *ff1, *y2, *h, *kn, *nrm, *c, *r;
    cudaGetSymbolAddress((void**)&h0,  g_h0);
    cudaGetSymbolAddress((void**)&ff1, g_ff1);
    cudaGetSymbolAddress((void**)&y2,  g_y2);
    cudaGetSymbolAddress((void**)&h,   g_h);
    cudaGetSymbolAddress((void**)&kn,  g_kn);
    cudaGetSymbolAddress((void**)&nrm, g_nrm);
    cudaGetSymbolAddress((void**)&c,   g_c);
    cudaGetSymbolAddress((void**)&r,   g_r);

    // 1. embedding gather
    k_gather<<<TOK, 128>>>(seq, embed, h0);
    // 2. FFN up (relu)   [16384 x 1024 x 512]
    k_gemm<1><<<dim3(2 * H / 128, TOK / 128), 256>>>(h0, ff_w1, ff_b1, ff1, 2 * H, H);
    // 3. FFN down        [16384 x 512 x 1024]
    k_gemm<0><<<dim3(H / 128, TOK / 128), 256>>>(ff1, ff_w2, ff_b2, y2, H, 2 * H);
    // 4. residual + layernorm
    k_ln<<<TOK / 8, 256>>>(y2, h0, gamma, beta, h);
    // 5+6. key projections, scattered to [l][b][c]
    k_gemm<2><<<dim3(HALF / 128, TOK / 128), 256>>>(h, sem_w, nullptr, kn, HALF, H);
    k_gemm<2><<<dim3(HALF / 128, TOK / 128), 256>>>(h, epi_w, nullptr,
                                                    kn + (size_t)L * B * HALF, HALF, H);
    // 7. normalize keys in place, stash clamped norms
    k_norm<<<(2 * L * B) / 8, 256>>>(kn, nrm);
    // 8. backward-query scan (O(L*HALF) per chain)
    k_scan<<<32, 32>>>(kn, nrm, c);
    // 9. readout projection
    k_rp<<<H / 16, 256>>>(c, rp_w, rp_b, r);
    // 10. logits
    k_out<<<V / 256, 256>>>(r, out_w, out_b, out);
}